// round 14
// baseline (speedup 1.0000x reference)
#include <cuda_runtime.h>
#include <cstdint>
#include <math.h>

// ---------------- problem constants ----------------
#define TOK    16384
#define DDIM   2048
#define NEXP   64
#define BLK_M  128
#define NBLK   (TOK / BLK_M)     // 128 blocks = one wave
#define KCH    32                // k floats per chunk
#define NCH    (DDIM / KCH)      // 64 chunks
#define NT     512               // 16 warps = 4 per SMSP

// smem staging (floats), pitch 36 = 32 data + 4 pad -> conflict-free frags
#define PITCH  36
#define A_HI   0
#define A_LO   (BLK_M * PITCH)                 // 4608
#define B_HI   (2 * BLK_M * PITCH)             // 9216
#define B_LO   (B_HI + NEXP * PITCH)           // 11520
#define STG_F  (B_LO + NEXP * PITCH)           // 13824 floats = 55296 B
#define SMEM_TOTAL (2 * STG_F * 4)             // 110592 B

// aux-loss partials + arrival counter (fused last-block reduction)
__device__ float g_pprob[NBLK * NEXP];
__device__ float g_pcnt [NBLK * NEXP];
__device__ unsigned int g_arrival = 0;

__device__ __forceinline__ float tf32_rn(float v) {
    uint32_t u; asm("cvt.rna.tf32.f32 %0, %1;" : "=r"(u) : "f"(v));
    return __uint_as_float(u);
}

// m16n8k8 tf32 MMA, D == C (accumulating)
__device__ __forceinline__ void mma1688(float* c, const uint32_t* a, const uint32_t* b) {
    asm volatile(
        "mma.sync.aligned.m16n8k8.row.col.f32.tf32.tf32.f32 "
        "{%0,%1,%2,%3}, {%4,%5,%6,%7}, {%8,%9}, {%0,%1,%2,%3};"
        : "+f"(c[0]), "+f"(c[1]), "+f"(c[2]), "+f"(c[3])
        : "r"(a[0]), "r"(a[1]), "r"(a[2]), "r"(a[3]), "r"(b[0]), "r"(b[1]));
}

struct Epi {
    float L[BLK_M * 65];
    float m1[BLK_M], rs[BLK_M];
    int   i1[BLK_M];
    int   flag;
    float rP[8][NEXP], rC[8][NEXP], red[NEXP];
};

__global__ void __launch_bounds__(NT, 1)
router_kernel(const float* __restrict__ x, const float* __restrict__ W,
              float* __restrict__ out)
{
    extern __shared__ __align__(16) float smf[];
    const int tid  = threadIdx.x;
    const int wid  = tid >> 5;
    const int lane = tid & 31;
    const int blk  = blockIdx.x;

    // ---- staging map: 3 x float4 per thread per chunk ----
    const float* sg[3];
    int sdst[3];                       // float offset within a stage
#pragma unroll
    for (int q = 0; q < 3; q++) {
        int f = q * NT + tid;          // 0..1535
        if (f < 1024) {                // x: 128 rows x 8 float4
            int row = f >> 3, c4 = f & 7;
            sg[q]   = x + (size_t)blk * BLK_M * DDIM + (size_t)row * DDIM + c4 * 4;
            sdst[q] = row * PITCH + c4 * 4;          // into A_HI/A_LO
        } else {                       // W: 64 rows x 8 float4
            int g = f - 1024, row = g >> 3, c4 = g & 7;
            sg[q]   = W + (size_t)row * DDIM + c4 * 4;
            sdst[q] = B_HI + row * PITCH + c4 * 4;   // B_LO = +NEXP*PITCH
        }
    }

    float4 pf[3];
#pragma unroll
    for (int q = 0; q < 3; q++) pf[q] = *(const float4*)sg[q];

    // ---- warp tile: warp_m 0..7 (16 tokens), warp_n 0..1 (32 experts) ----
    const int m0 = (wid >> 1) * 16;
    const int n0 = (wid & 1) * 32;
    const int g  = lane >> 2;          // groupID 0..7
    const int tg = lane & 3;           // thread-in-group 0..3

    float acc[4][4];
#pragma unroll
    for (int nt = 0; nt < 4; nt++)
#pragma unroll
        for (int r = 0; r < 4; r++) acc[nt][r] = 0.0f;

    for (int c = 0; c < NCH; c++) {
        float* st = smf + (c & 1) * STG_F;
        // split + store staged chunk (hi to *_HI, residual lo to *_LO)
#pragma unroll
        for (int q = 0; q < 3; q++) {
            float4 v = pf[q], h, l;
            h.x = tf32_rn(v.x); l.x = tf32_rn(v.x - h.x);
            h.y = tf32_rn(v.y); l.y = tf32_rn(v.y - h.y);
            h.z = tf32_rn(v.z); l.z = tf32_rn(v.z - h.z);
            h.w = tf32_rn(v.w); l.w = tf32_rn(v.w - h.w);
            int lo_off = (q < 2) ? (A_LO - A_HI) : (B_LO - B_HI);
            *(float4*)(st + sdst[q])          = h;
            *(float4*)(st + sdst[q] + lo_off) = l;
        }
        // prefetch next chunk while MMAs run
        if (c + 1 < NCH) {
            int off = (c + 1) * KCH;
#pragma unroll
            for (int q = 0; q < 3; q++) pf[q] = *(const float4*)(sg[q] + off);
        }
        __syncthreads();   // staged data visible; also orders MMA(c-1) vs this STS

        const uint32_t* su = (const uint32_t*)st;
#pragma unroll
        for (int ks = 0; ks < 4; ks++) {
            const int k0 = ks * 8;
            uint32_t ah[4], al[4];
            {
                int r = (m0 + g) * PITCH + k0 + tg;
                ah[0] = su[A_HI + r];
                ah[1] = su[A_HI + r + 8 * PITCH];
                ah[2] = su[A_HI + r + 4];
                ah[3] = su[A_HI + r + 8 * PITCH + 4];
                al[0] = su[A_LO + r];
                al[1] = su[A_LO + r + 8 * PITCH];
                al[2] = su[A_LO + r + 4];
                al[3] = su[A_LO + r + 8 * PITCH + 4];
            }
            uint32_t bh[4][2], bl[4][2];
#pragma unroll
            for (int nt = 0; nt < 4; nt++) {
                int r = (n0 + nt * 8 + g) * PITCH + k0 + tg;
                bh[nt][0] = su[B_HI + r];
                bh[nt][1] = su[B_HI + r + 4];
                bl[nt][0] = su[B_LO + r];
                bl[nt][1] = su[B_LO + r + 4];
            }
#pragma unroll
            for (int nt = 0; nt < 4; nt++) {
                mma1688(acc[nt], al, bh[nt]);   // lo*hi
                mma1688(acc[nt], ah, bl[nt]);   // hi*lo
                mma1688(acc[nt], ah, bh[nt]);   // hi*hi
            }
        }
    }
    __syncthreads();       // all smem reads done before epilogue overlay

    Epi* ep = (Epi*)smf;
    // ---- spill logits: D frag (nt): rows m0+g(+8), cols n0+nt*8+2tg(+1)
    {
        int r = m0 + g;
#pragma unroll
        for (int nt = 0; nt < 4; nt++) {
            int col = n0 + nt * 8 + 2 * tg;
            ep->L[r * 65 + col]           = acc[nt][0];
            ep->L[r * 65 + col + 1]       = acc[nt][1];
            ep->L[(r + 8) * 65 + col]     = acc[nt][2];
            ep->L[(r + 8) * 65 + col + 1] = acc[nt][3];
        }
    }
    __syncthreads();

    // one thread per token: top-2 (strict >, lowest index on ties, like lax.top_k)
    if (tid < BLK_M) {
        const float* row = ep->L + tid * 65;
        float m1 = -3.402823466e38f, m2 = -3.402823466e38f;
        int i1 = 0, i2 = 0;
#pragma unroll
        for (int e = 0; e < NEXP; e++) {
            float v = row[e];
            if (v > m1)      { m2 = m1; i2 = i1; m1 = v; i1 = e; }
            else if (v > m2) { m2 = v; i2 = e; }
        }
        float s = 0.0f;
#pragma unroll
        for (int e = 0; e < NEXP; e++) s += __expf(row[e] - m1);

        ep->m1[tid] = m1;
        ep->rs[tid] = 1.0f / s;
        ep->i1[tid] = i1;

        int gg = blk * BLK_M + tid;
        float q   = __expf(m2 - m1);
        float inv = 1.0f / (1.0f + q);
        out[2 * gg]               = (float)i1;   // top_k_indices
        out[2 * gg + 1]           = (float)i2;
        out[2 * TOK + 2 * gg]     = inv;         // top_k_weights
        out[2 * TOK + 2 * gg + 1] = q * inv;
    }
    __syncthreads();

    // one thread per expert: deterministic per-block prob-sum / top-1 count
    if (tid < NEXP) {
        float ps = 0.0f, cs = 0.0f;
#pragma unroll 8
        for (int t = 0; t < BLK_M; t++) {
            ps += __expf(ep->L[t * 65 + tid] - ep->m1[t]) * ep->rs[t];
            cs += (ep->i1[t] == tid) ? 1.0f : 0.0f;
        }
        g_pprob[blk * NEXP + tid] = ps;
        g_pcnt [blk * NEXP + tid] = cs;
    }
    __syncthreads();

    // ---- fused aux loss: last-arriving block folds all partials ----
    if (tid == 0) {
        __threadfence();
        unsigned old = atomicAdd(&g_arrival, 1u);
        ep->flag = (old == NBLK - 1) ? 1 : 0;
    }
    __syncthreads();
    if (ep->flag) {
        __threadfence();
        int e = tid & 63, h = tid >> 6;       // 8 parts x 16 blocks
        float sp = 0.0f, sc = 0.0f;
        int b0 = h * (NBLK / 8);
#pragma unroll 8
        for (int b = b0; b < b0 + NBLK / 8; b++) {
            sp += g_pprob[b * NEXP + e];
            sc += g_pcnt [b * NEXP + e];
        }
        ep->rP[h][e] = sp;
        ep->rC[h][e] = sc;
        __syncthreads();
        if (tid < NEXP) {
            float P = 0.0f, C = 0.0f;
#pragma unroll
            for (int hh = 0; hh < 8; hh++) { P += ep->rP[hh][tid]; C += ep->rC[hh][tid]; }
            ep->red[tid] = (C * (1.0f / TOK)) * (P * (1.0f / TOK));
        }
        __syncthreads();
        if (tid == 0) {
            float s = 0.0f;
            for (int k = 0; k < NEXP; k++) s += ep->red[k];
            out[4 * TOK] = (float)NEXP * s * 0.01f;  // E * sum * aux_w
            g_arrival = 0;                            // reset for next graph replay
        }
    }
}

extern "C" void kernel_launch(void* const* d_in, const int* in_sizes, int n_in,
                              void* d_out, int out_size)
{
    const float* x = (const float*)d_in[0];
    const float* W = (const float*)d_in[1];
    if (n_in >= 2 && in_sizes[0] == NEXP * DDIM && in_sizes[1] == TOK * DDIM) {
        const float* t = x; x = W; W = t;
    }
    cudaFuncSetAttribute(router_kernel,
                         cudaFuncAttributeMaxDynamicSharedMemorySize, SMEM_TOTAL);
    router_kernel<<<NBLK, NT, SMEM_TOTAL>>>(x, W, (float*)d_out);
}

// round 15
// speedup vs baseline: 1.0829x; 1.0829x over previous
#include <cuda_runtime.h>
#include <cstdint>
#include <math.h>

// ---------------- problem constants ----------------
#define TOK    16384
#define DDIM   2048
#define NEXP   64
#define BLK_M  128
#define NBLK   (TOK / BLK_M)     // 128 blocks = one wave
#define KCH    32                // k floats per chunk
#define NCH    (DDIM / KCH)      // 64 chunks
#define NT     512               // 2 role groups x 8 warps

// smem staging (floats), pitch 36 = 32 data + 4 pad -> conflict-free frags
#define PITCH  36
#define A_HI   0
#define A_LO   (BLK_M * PITCH)                 // 4608
#define B_HI   (2 * BLK_M * PITCH)             // 9216
#define B_LO   (B_HI + NEXP * PITCH)           // 11520
#define STG_F  (B_LO + NEXP * PITCH)           // 13824 floats = 55296 B
#define SMEM_TOTAL (2 * STG_F * 4)             // 110592 B

// aux-loss partials + arrival counter (fused last-block reduction)
__device__ float g_pprob[NBLK * NEXP];
__device__ float g_pcnt [NBLK * NEXP];
__device__ unsigned int g_arrival = 0;

__device__ __forceinline__ float tf32_rn(float v) {
    uint32_t u; asm("cvt.rna.tf32.f32 %0, %1;" : "=r"(u) : "f"(v));
    return __uint_as_float(u);
}

// m16n8k8 tf32 MMA, D == C (accumulating)
__device__ __forceinline__ void mma1688(float* c, const uint32_t* a, const uint32_t* b) {
    asm volatile(
        "mma.sync.aligned.m16n8k8.row.col.f32.tf32.tf32.f32 "
        "{%0,%1,%2,%3}, {%4,%5,%6,%7}, {%8,%9}, {%0,%1,%2,%3};"
        : "+f"(c[0]), "+f"(c[1]), "+f"(c[2]), "+f"(c[3])
        : "r"(a[0]), "r"(a[1]), "r"(a[2]), "r"(a[3]), "r"(b[0]), "r"(b[1]));
}

struct Epi {
    float L[BLK_M * 65];
    float m1[BLK_M], rs[BLK_M];
    int   i1[BLK_M];
    int   flag;
    float rP[8][NEXP], rC[8][NEXP], red[NEXP];
};

__device__ __forceinline__ void store_stage(float* st, const float4* pf, const int* sdst) {
#pragma unroll
    for (int q = 0; q < 6; q++) {
        float4 v = pf[q], h, l;
        h.x = tf32_rn(v.x); l.x = tf32_rn(v.x - h.x);
        h.y = tf32_rn(v.y); l.y = tf32_rn(v.y - h.y);
        h.z = tf32_rn(v.z); l.z = tf32_rn(v.z - h.z);
        h.w = tf32_rn(v.w); l.w = tf32_rn(v.w - h.w);
        int lo_off = (q < 4) ? (A_LO - A_HI) : (B_LO - B_HI);
        *(float4*)(st + sdst[q])          = h;
        *(float4*)(st + sdst[q] + lo_off) = l;
    }
}

__global__ void __launch_bounds__(NT, 1)
router_kernel(const float* __restrict__ x, const float* __restrict__ W,
              float* __restrict__ out)
{
    extern __shared__ __align__(16) float smf[];
    const int tid  = threadIdx.x;
    const int wid  = tid >> 5;
    const int lane = tid & 31;
    const int blk  = blockIdx.x;
    const int grp  = wid >> 3;         // 0: warps 0-7, 1: warps 8-15
    const int ltid = tid & 255;        // id within role group

    // ---- staging map (per 256-thread group): 6 x float4 per chunk ----
    const float* sg[6];
    int sdst[6];
#pragma unroll
    for (int q = 0; q < 6; q++) {
        int f = q * 256 + ltid;        // 0..1535
        if (f < 1024) {                // x: 128 rows x 8 float4
            int row = f >> 3, c4 = f & 7;
            sg[q]   = x + (size_t)blk * BLK_M * DDIM + (size_t)row * DDIM + c4 * 4;
            sdst[q] = row * PITCH + c4 * 4;
        } else {                       // W: 64 rows x 8 float4
            int g2 = f - 1024, row = g2 >> 3, c4 = g2 & 7;
            sg[q]   = W + (size_t)row * DDIM + c4 * 4;
            sdst[q] = B_HI + row * PITCH + c4 * 4;
        }
    }

    // ---- warp tile within group (R13 geometry): 32 tokens x 32 experts ----
    const int wl = wid & 7;
    const int m0 = (wl >> 1) * 32;
    const int n0 = (wl & 1) * 32;
    const int g  = lane >> 2;          // groupID 0..7
    const int tg = lane & 3;           // thread-in-group 0..3

    float acc[2][4][4];
#pragma unroll
    for (int mt = 0; mt < 2; mt++)
#pragma unroll
        for (int nt = 0; nt < 4; nt++)
#pragma unroll
            for (int r = 0; r < 4; r++) acc[mt][nt][r] = 0.0f;

    float4 pf[6];
    // ---- prologue: A loads+stores chunk 0; B loads chunk 1 (stores at iter 0)
    if (grp == 0) {
#pragma unroll
        for (int q = 0; q < 6; q++) pf[q] = *(const float4*)sg[q];
        store_stage(smf, pf, sdst);                 // chunk 0 -> buf0
    } else {
#pragma unroll
        for (int q = 0; q < 6; q++) pf[q] = *(const float4*)(sg[q] + KCH);
    }
    __syncthreads();

    // ---- main loop: one group MMAs chunk c while the other stages chunk c+1 ----
    for (int c = 0; c < NCH; c++) {
        if ((c & 1) == grp) {
            // prefetch my next staging duty (chunk c+2) while tensor pipe works
            if (c + 2 < NCH) {
                const int off = (c + 2) * KCH;
#pragma unroll
                for (int q = 0; q < 6; q++) pf[q] = *(const float4*)(sg[q] + off);
            }
            const uint32_t* su = (const uint32_t*)(smf + (c & 1) * STG_F);
#pragma unroll
            for (int ks = 0; ks < 4; ks++) {
                const int k0 = ks * 8;
                uint32_t ah[2][4], al[2][4];
#pragma unroll
                for (int mt = 0; mt < 2; mt++) {
                    int r = (m0 + mt * 16 + g) * PITCH + k0 + tg;
                    ah[mt][0] = su[A_HI + r];
                    ah[mt][1] = su[A_HI + r + 8 * PITCH];
                    ah[mt][2] = su[A_HI + r + 4];
                    ah[mt][3] = su[A_HI + r + 8 * PITCH + 4];
                    al[mt][0] = su[A_LO + r];
                    al[mt][1] = su[A_LO + r + 8 * PITCH];
                    al[mt][2] = su[A_LO + r + 4];
                    al[mt][3] = su[A_LO + r + 8 * PITCH + 4];
                }
                uint32_t bh[4][2], bl[4][2];
#pragma unroll
                for (int nt = 0; nt < 4; nt++) {
                    int r = (n0 + nt * 8 + g) * PITCH + k0 + tg;
                    bh[nt][0] = su[B_HI + r];
                    bh[nt][1] = su[B_HI + r + 4];
                    bl[nt][0] = su[B_LO + r];
                    bl[nt][1] = su[B_LO + r + 4];
                }
#pragma unroll
                for (int mt = 0; mt < 2; mt++)
#pragma unroll
                    for (int nt = 0; nt < 4; nt++) {
                        mma1688(acc[mt][nt], al[mt], bh[nt]);   // lo*hi
                        mma1688(acc[mt][nt], ah[mt], bl[nt]);   // hi*lo
                        mma1688(acc[mt][nt], ah[mt], bh[nt]);   // hi*hi
                    }
            }
        } else {
            // stage chunk c+1 (held in pf since last iteration) into the other buffer
            if (c + 1 < NCH)
                store_stage(smf + ((c + 1) & 1) * STG_F, pf, sdst);
        }
        __syncthreads();
    }

    // ---- merge the two groups' partial accumulators, then epilogue ----
    Epi* ep = (Epi*)smf;
    if (grp == 1) {
#pragma unroll
        for (int mt = 0; mt < 2; mt++) {
            int r = m0 + mt * 16 + g;
#pragma unroll
            for (int nt = 0; nt < 4; nt++) {
                int col = n0 + nt * 8 + 2 * tg;
                ep->L[r * 65 + col]           = acc[mt][nt][0];
                ep->L[r * 65 + col + 1]       = acc[mt][nt][1];
                ep->L[(r + 8) * 65 + col]     = acc[mt][nt][2];
                ep->L[(r + 8) * 65 + col + 1] = acc[mt][nt][3];
            }
        }
    }
    __syncthreads();
    if (grp == 0) {
#pragma unroll
        for (int mt = 0; mt < 2; mt++) {
            int r = m0 + mt * 16 + g;
#pragma unroll
            for (int nt = 0; nt < 4; nt++) {
                int col = n0 + nt * 8 + 2 * tg;
                ep->L[r * 65 + col]           += acc[mt][nt][0];
                ep->L[r * 65 + col + 1]       += acc[mt][nt][1];
                ep->L[(r + 8) * 65 + col]     += acc[mt][nt][2];
                ep->L[(r + 8) * 65 + col + 1] += acc[mt][nt][3];
            }
        }
    }
    __syncthreads();

    // one thread per token: top-2 (strict >, lowest index on ties, like lax.top_k)
    if (tid < BLK_M) {
        const float* row = ep->L + tid * 65;
        float m1 = -3.402823466e38f, m2 = -3.402823466e38f;
        int i1 = 0, i2 = 0;
#pragma unroll
        for (int e = 0; e < NEXP; e++) {
            float v = row[e];
            if (v > m1)      { m2 = m1; i2 = i1; m1 = v; i1 = e; }
            else if (v > m2) { m2 = v; i2 = e; }
        }
        float s = 0.0f;
#pragma unroll
        for (int e = 0; e < NEXP; e++) s += __expf(row[e] - m1);

        ep->m1[tid] = m1;
        ep->rs[tid] = 1.0f / s;
        ep->i1[tid] = i1;

        int gg = blk * BLK_M + tid;
        float q   = __expf(m2 - m1);
        float inv = 1.0f / (1.0f + q);
        out[2 * gg]               = (float)i1;   // top_k_indices
        out[2 * gg + 1]           = (float)i2;
        out[2 * TOK + 2 * gg]     = inv;         // top_k_weights
        out[2 * TOK + 2 * gg + 1] = q * inv;
    }
    __syncthreads();

    // one thread per expert: deterministic per-block prob-sum / top-1 count
    if (tid < NEXP) {
        float ps = 0.0f, cs = 0.0f;
#pragma unroll 8
        for (int t = 0; t < BLK_M; t++) {
            ps += __expf(ep->L[t * 65 + tid] - ep->m1[t]) * ep->rs[t];
            cs += (ep->i1[t] == tid) ? 1.0f : 0.0f;
        }
        g_pprob[blk * NEXP + tid] = ps;
        g_pcnt [blk * NEXP + tid] = cs;
    }
    __syncthreads();

    // ---- fused aux loss: last-arriving block folds all partials ----
    if (tid == 0) {
        __threadfence();
        unsigned old = atomicAdd(&g_arrival, 1u);
        ep->flag = (old == NBLK - 1) ? 1 : 0;
    }
    __syncthreads();
    if (ep->flag) {
        __threadfence();
        int e = tid & 63, h = tid >> 6;       // 8 parts x 16 blocks
        float sp = 0.0f, sc = 0.0f;
        int b0 = h * (NBLK / 8);
#pragma unroll 8
        for (int b = b0; b < b0 + NBLK / 8; b++) {
            sp += g_pprob[b * NEXP + e];
            sc += g_pcnt [b * NEXP + e];
        }
        ep->rP[h][e] = sp;
        ep->rC[h][e] = sc;
        __syncthreads();
        if (tid < NEXP) {
            float P = 0.0f, C = 0.0f;
#pragma unroll
            for (int hh = 0; hh < 8; hh++) { P += ep->rP[hh][tid]; C += ep->rC[hh][tid]; }
            ep->red[tid] = (C * (1.0f / TOK)) * (P * (1.0f / TOK));
        }
        __syncthreads();
        if (tid == 0) {
            float s = 0.0f;
            for (int k = 0; k < NEXP; k++) s += ep->red[k];
            out[4 * TOK] = (float)NEXP * s * 0.01f;  // E * sum * aux_w
            g_arrival = 0;                            // reset for next graph replay
        }
    }
}

extern "C" void kernel_launch(void* const* d_in, const int* in_sizes, int n_in,
                              void* d_out, int out_size)
{
    const float* x = (const float*)d_in[0];
    const float* W = (const float*)d_in[1];
    if (n_in >= 2 && in_sizes[0] == NEXP * DDIM && in_sizes[1] == TOK * DDIM) {
        const float* t = x; x = W; W = t;
    }
    cudaFuncSetAttribute(router_kernel,
                         cudaFuncAttributeMaxDynamicSharedMemorySize, SMEM_TOTAL);
    router_kernel<<<NBLK, NT, SMEM_TOTAL>>>(x, W, (float*)d_out);
}

// round 16
// speedup vs baseline: 1.0833x; 1.0003x over previous
#include <cuda_runtime.h>
#include <cstdint>
#include <math.h>

// ---------------- problem constants ----------------
#define TOK    16384
#define DDIM   2048
#define NEXP   64
#define BLK_M  128
#define NBLK   (TOK / BLK_M)     // 128 blocks = one wave
#define KCH    32                // k floats per chunk
#define NCH    (DDIM / KCH)      // 64 chunks
#define NT     256               // 8 warps, 32x32 warp tiles

// ---- fragment-native smem layouts ----
// A: 64 pair-rows (band b=pr>>3, g=pr&7 <-> rows b*16+g, b*16+g+8), word =
//    {A[r][k], A[r+8][k], A[r][k+1], A[r+8][k+1]}; pitch 72 floats (64+8 pad)
// B: 64 rows, k-permuted: word = {B[n][k], B[n][k+4], B[n][k+1], B[n][k+5]};
//    pitch 40 floats (32+8 pad)
#define PA     72
#define PB     40
#define A_HI_F 0
#define A_LO_F 4608                    // 64*72
#define B_HI_F 9216
#define B_LO_F 11776                   // 9216 + 64*40
#define STG_F  14336                   // floats per stage (57344 B)
#define SMEM_TOTAL (2 * STG_F * 4)     // 114688 B

// aux-loss partials + arrival counter (fused last-block reduction)
__device__ float g_pprob[NBLK * NEXP];
__device__ float g_pcnt [NBLK * NEXP];
__device__ unsigned int g_arrival = 0;

__device__ __forceinline__ float tf32_rn(float v) {
    uint32_t u; asm("cvt.rna.tf32.f32 %0, %1;" : "=r"(u) : "f"(v));
    return __uint_as_float(u);
}

// m16n8k8 tf32 MMA, D == C (accumulating)
__device__ __forceinline__ void mma1688(float* c, const uint32_t* a, const uint32_t* b) {
    asm volatile(
        "mma.sync.aligned.m16n8k8.row.col.f32.tf32.tf32.f32 "
        "{%0,%1,%2,%3}, {%4,%5,%6,%7}, {%8,%9}, {%0,%1,%2,%3};"
        : "+f"(c[0]), "+f"(c[1]), "+f"(c[2]), "+f"(c[3])
        : "r"(a[0]), "r"(a[1]), "r"(a[2]), "r"(a[3]), "r"(b[0]), "r"(b[1]));
}

struct Epi {
    float L[BLK_M * 65];
    float m1[BLK_M], rs[BLK_M];
    int   i1[BLK_M];
    int   flag;
    float rP[4][NEXP], rC[4][NEXP], red[NEXP];
};

__global__ void __launch_bounds__(NT, 1)
router_kernel(const float* __restrict__ x, const float* __restrict__ W,
              float* __restrict__ out)
{
    extern __shared__ __align__(16) float smf[];
    const int tid  = threadIdx.x;
    const int wid  = tid >> 5;
    const int lane = tid & 31;
    const int blk  = blockIdx.x;

    // ---- staging map: 6 words/thread; each word = 2x LDG.64 -> 2x STS.128 ----
    // words 0..1023: A (pr 0..63, j 0..15, k = 2j); 1024..1535: B (n 0..63, w8 0..7)
    const float* g0[6]; const float* g1[6];
    int dh[6], dl[6];
#pragma unroll
    for (int q = 0; q < 6; q++) {
        int w = q * NT + tid;
        if (w < 1024) {
            int pr = w >> 4, j = w & 15;
            int b = pr >> 3, gg = pr & 7;
            const float* base = x + (size_t)blk * BLK_M * DDIM
                                  + (size_t)(b * 16 + gg) * DDIM + 2 * j;
            g0[q] = base;                 // row r,   k..k+1
            g1[q] = base + 8 * DDIM;      // row r+8, k..k+1
            dh[q] = A_HI_F + pr * PA + j * 4;
            dl[q] = A_LO_F - A_HI_F;
        } else {
            int v = w - 1024, n = v >> 3, w8 = v & 7;
            int k = (w8 >> 1) * 8 + (w8 & 1) * 2;
            const float* base = W + (size_t)n * DDIM + k;
            g0[q] = base;                 // k..k+1
            g1[q] = base + 4;             // k+4..k+5
            dh[q] = B_HI_F + n * PB + w8 * 4;
            dl[q] = B_LO_F - B_HI_F;
        }
    }

    float2 p0[6], p1[6];
#pragma unroll
    for (int q = 0; q < 6; q++) { p0[q] = *(const float2*)g0[q]; p1[q] = *(const float2*)g1[q]; }

    // ---- warp tile: 32 tokens x 32 experts ----
    const int m0  = (wid >> 1) * 32;
    const int n0w = (wid & 1) * 32;
    const int g   = lane >> 2;
    const int tg  = lane & 3;

    float acc[2][4][4];
#pragma unroll
    for (int mt = 0; mt < 2; mt++)
#pragma unroll
        for (int nt = 0; nt < 4; nt++)
#pragma unroll
            for (int r = 0; r < 4; r++) acc[mt][nt][r] = 0.0f;

    for (int c = 0; c < NCH; c++) {
        float* st = smf + (c & 1) * STG_F;
        // split + store (word order {v0,v1,v2,v3} = {r0.x, r1.x, r0.y, r1.y})
#pragma unroll
        for (int q = 0; q < 6; q++) {
            float v0 = p0[q].x, v1 = p1[q].x, v2 = p0[q].y, v3 = p1[q].y;
            float4 h, l;
            h.x = tf32_rn(v0); l.x = tf32_rn(v0 - h.x);
            h.y = tf32_rn(v1); l.y = tf32_rn(v1 - h.y);
            h.z = tf32_rn(v2); l.z = tf32_rn(v2 - h.z);
            h.w = tf32_rn(v3); l.w = tf32_rn(v3 - h.w);
            *(float4*)(st + dh[q])         = h;
            *(float4*)(st + dh[q] + dl[q]) = l;
        }
        // prefetch next chunk while MMAs run
        if (c + 1 < NCH) {
            int off = (c + 1) * KCH;
#pragma unroll
            for (int q = 0; q < 6; q++) {
                p0[q] = *(const float2*)(g0[q] + off);
                p1[q] = *(const float2*)(g1[q] + off);
            }
        }
        __syncthreads();   // stage(c) visible; also separates MMA(c-2) from this STS

        // frag base pointers (immediate offsets from here on)
        const char* aP = (const char*)st + (size_t)(((wid >> 1) * 16 + g) * PA) * 4;
        const char* bP = (const char*)st + (size_t)(B_HI_F + (n0w + g) * PB) * 4;

        uint32_t ah[2][2][4], al[2][2][4], bh[2][4][2], bl[2][4][2];

#define LOADFRAG(BUF, KS) do {                                                  \
    _Pragma("unroll")                                                           \
    for (int mt = 0; mt < 2; mt++) {                                            \
        const char* ap = aP + mt * 2304 + (KS) * 64 + tg * 8;                   \
        uint2 h0 = *(const uint2*)(ap);                                         \
        uint2 h1 = *(const uint2*)(ap + 32);                                    \
        uint2 l0 = *(const uint2*)(ap + 18432);                                 \
        uint2 l1 = *(const uint2*)(ap + 18464);                                 \
        ah[BUF][mt][0] = h0.x; ah[BUF][mt][1] = h0.y;                           \
        ah[BUF][mt][2] = h1.x; ah[BUF][mt][3] = h1.y;                           \
        al[BUF][mt][0] = l0.x; al[BUF][mt][1] = l0.y;                           \
        al[BUF][mt][2] = l1.x; al[BUF][mt][3] = l1.y;                           \
    }                                                                           \
    _Pragma("unroll")                                                           \
    for (int nt = 0; nt < 4; nt++) {                                            \
        const char* bp = bP + nt * 1280 + (KS) * 32 + tg * 8;                   \
        uint2 hb = *(const uint2*)(bp);                                         \
        uint2 lb = *(const uint2*)(bp + 10240);                                 \
        bh[BUF][nt][0] = hb.x; bh[BUF][nt][1] = hb.y;                           \
        bl[BUF][nt][0] = lb.x; bl[BUF][nt][1] = lb.y;                           \
    }                                                                           \
} while (0)

        LOADFRAG(0, 0);
#pragma unroll
        for (int ks = 0; ks < 4; ks++) {
            if (ks < 3) {                       // load next kstep into other buffer
                if ((ks & 1) == 0) LOADFRAG(1, ks + 1);
                else               LOADFRAG(0, ks + 1);
            }
            const int b = ks & 1;
#pragma unroll
            for (int mt = 0; mt < 2; mt++)
#pragma unroll
                for (int nt = 0; nt < 4; nt++) {
                    mma1688(acc[mt][nt], al[b][mt], bh[b][nt]);   // lo*hi
                    mma1688(acc[mt][nt], ah[b][mt], bl[b][nt]);   // hi*lo
                    mma1688(acc[mt][nt], ah[b][mt], bh[b][nt]);   // hi*hi
                }
        }
#undef LOADFRAG
    }
    __syncthreads();       // all smem reads done before epilogue overlay

    Epi* ep = (Epi*)smf;
    // ---- spill logits: frag (mt,nt): rows m0+mt*16+g(+8), cols n0w+nt*8+2tg(+1)
#pragma unroll
    for (int mt = 0; mt < 2; mt++) {
        int r = m0 + mt * 16 + g;
#pragma unroll
        for (int nt = 0; nt < 4; nt++) {
            int col = n0w + nt * 8 + 2 * tg;
            ep->L[r * 65 + col]           = acc[mt][nt][0];
            ep->L[r * 65 + col + 1]       = acc[mt][nt][1];
            ep->L[(r + 8) * 65 + col]     = acc[mt][nt][2];
            ep->L[(r + 8) * 65 + col + 1] = acc[mt][nt][3];
        }
    }
    __syncthreads();

    // one thread per token: top-2 (strict >, lowest index on ties, like lax.top_k)
    if (tid < BLK_M) {
        const float* row = ep->L + tid * 65;
        float m1 = -3.402823466e38f, m2 = -3.402823466e38f;
        int i1 = 0, i2 = 0;
#pragma unroll
        for (int e = 0; e < NEXP; e++) {
            float v = row[e];
            if (v > m1)      { m2 = m1; i2 = i1; m1 = v; i1 = e; }
            else if (v > m2) { m2 = v; i2 = e; }
        }
        float s = 0.0f;
#pragma unroll
        for (int e = 0; e < NEXP; e++) s += __expf(row[e] - m1);

        ep->m1[tid] = m1;
        ep->rs[tid] = 1.0f / s;
        ep->i1[tid] = i1;

        int gg = blk * BLK_M + tid;
        float q   = __expf(m2 - m1);
        float inv = 1.0f / (1.0f + q);
        out[2 * gg]               = (float)i1;   // top_k_indices
        out[2 * gg + 1]           = (float)i2;
        out[2 * TOK + 2 * gg]     = inv;         // top_k_weights
        out[2 * TOK + 2 * gg + 1] = q * inv;
    }
    __syncthreads();

    // one thread per expert: deterministic per-block prob-sum / top-1 count
    if (tid < NEXP) {
        float ps = 0.0f, cs = 0.0f;
#pragma unroll 8
        for (int t = 0; t < BLK_M; t++) {
            ps += __expf(ep->L[t * 65 + tid] - ep->m1[t]) * ep->rs[t];
            cs += (ep->i1[t] == tid) ? 1.0f : 0.0f;
        }
        g_pprob[blk * NEXP + tid] = ps;
        g_pcnt [blk * NEXP + tid] = cs;
    }
    __syncthreads();

    // ---- fused aux loss: last-arriving block folds all partials ----
    if (tid == 0) {
        __threadfence();
        unsigned old = atomicAdd(&g_arrival, 1u);
        ep->flag = (old == NBLK - 1) ? 1 : 0;
    }
    __syncthreads();
    if (ep->flag) {
        __threadfence();
        int e = tid & 63, h = tid >> 6;       // 4 parts x 32 blocks
        float sp = 0.0f, sc = 0.0f;
        int b0 = h * (NBLK / 4);
#pragma unroll 8
        for (int b = b0; b < b0 + NBLK / 4; b++) {
            sp += g_pprob[b * NEXP + e];
            sc += g_pcnt [b * NEXP + e];
        }
        ep->rP[h][e] = sp;
        ep->rC[h][e] = sc;
        __syncthreads();
        if (tid < NEXP) {
            float P = ep->rP[0][tid] + ep->rP[1][tid] + ep->rP[2][tid] + ep->rP[3][tid];
            float C = ep->rC[0][tid] + ep->rC[1][tid] + ep->rC[2][tid] + ep->rC[3][tid];
            ep->red[tid] = (C * (1.0f / TOK)) * (P * (1.0f / TOK));
        }
        __syncthreads();
        if (tid == 0) {
            float s = 0.0f;
            for (int k = 0; k < NEXP; k++) s += ep->red[k];
            out[4 * TOK] = (float)NEXP * s * 0.01f;  // E * sum * aux_w
            g_arrival = 0;                            // reset for next graph replay
        }
    }
}

extern "C" void kernel_launch(void* const* d_in, const int* in_sizes, int n_in,
                              void* d_out, int out_size)
{
    const float* x = (const float*)d_in[0];
    const float* W = (const float*)d_in[1];
    if (n_in >= 2 && in_sizes[0] == NEXP * DDIM && in_sizes[1] == TOK * DDIM) {
        const float* t = x; x = W; W = t;
    }
    cudaFuncSetAttribute(router_kernel,
                         cudaFuncAttributeMaxDynamicSharedMemorySize, SMEM_TOTAL);
    router_kernel<<<NBLK, NT, SMEM_TOTAL>>>(x, W, (float*)d_out);
}